// round 5
// baseline (speedup 1.0000x reference)
#include <cuda_runtime.h>
#include <cuda_bf16.h>

// Problem constants
#define NN 50000
#define EE 800000
#define BB 2
#define TT 12
#define HH 16
#define T1 10          // T-2
#define T2 8           // T-4
#define BT1 (BB*T1)    // 20
#define ROW (BT1*HH)   // 320 floats per node for h1/agg

// Scratch (node-major layout: [n][b][t][h]).  h2 overwrites g_h1 in place.
__device__ float g_h1[(size_t)NN * ROW];
__device__ float g_agg[(size_t)NN * ROW];
__device__ float g_norm[EE];
__device__ float g_deg[NN];
__device__ float g_dis[NN];
__device__ int   g_src[EE];
__device__ int   g_dst[EE];
__device__ int   g_oddnz;   // >0 => edge_index is int32; ==0 => int64

// Two identical repeat macros so they can nest (a macro cannot re-expand itself).
#define RPT16A(M) M(0) M(1) M(2) M(3) M(4) M(5) M(6) M(7) \
                  M(8) M(9) M(10) M(11) M(12) M(13) M(14) M(15)
#define RPT16B(M) M(0) M(1) M(2) M(3) M(4) M(5) M(6) M(7) \
                  M(8) M(9) M(10) M(11) M(12) M(13) M(14) M(15)

// ---------------------------------------------------------------------------
// K0: zero deg + agg + detector counter
__global__ void k_zero() {
    int i = blockIdx.x * blockDim.x + threadIdx.x;
    if (i == 0) g_oddnz = 0;
    if (i < NN) g_deg[i] = 0.f;
    if (i < (NN * ROW) / 4) ((float4*)g_agg)[i] = make_float4(0.f, 0.f, 0.f, 0.f);
}

// K0b: detect dtype of edge_index (odd int32 words all zero <=> int64).
__global__ void k_detect(const int* __restrict__ w) {
    int i = blockIdx.x * blockDim.x + threadIdx.x;   // 4096 threads
    int v = w[2 * i + 1];
    unsigned ballot = __ballot_sync(0xFFFFFFFFu, v != 0);
    if ((threadIdx.x & 31) == 0 && ballot) atomicAdd(&g_oddnz, __popc(ballot));
}

// K0c: unpack edge_index into int32 src/dst using detected layout.
__global__ void k_convert(const int* __restrict__ w) {
    int e = blockIdx.x * blockDim.x + threadIdx.x;
    if (e >= EE) return;
    if (g_oddnz == 0) {  // int64
        g_src[e] = w[2 * e];
        g_dst[e] = w[2 * EE + 2 * e];
    } else {             // int32
        g_src[e] = w[e];
        g_dst[e] = w[EE + e];
    }
}

// K1: deg[src] += w
__global__ void k_deg(const float* __restrict__ ew) {
    int e = blockIdx.x * blockDim.x + threadIdx.x;
    if (e >= EE) return;
    atomicAdd(&g_deg[g_src[e]], ew[e]);
}

// K2: dis = deg>0 ? rsqrt(max(deg,1e-12)) : 0
__global__ void k_dis() {
    int n = blockIdx.x * blockDim.x + threadIdx.x;
    if (n >= NN) return;
    float d = g_deg[n];
    g_dis[n] = (d > 0.f) ? rsqrtf(fmaxf(d, 1e-12f)) : 0.f;
}

// K3: norm[e] = -dis[src]*w*dis[dst]
__global__ void k_norm(const float* __restrict__ ew) {
    int e = blockIdx.x * blockDim.x + threadIdx.x;
    if (e >= EE) return;
    g_norm[e] = -g_dis[g_src[e]] * ew[e] * g_dis[g_dst[e]];
}

// K4: temporal conv 1 (GLU), C_IN=1 -> H=16.
// Thread per (n, bt); writes a contiguous 64B chunk via 4x float4.
__global__ void k_stage1(const float* __restrict__ x,
                         const float* __restrict__ wP, const float* __restrict__ bP,
                         const float* __restrict__ wQ, const float* __restrict__ bQ,
                         const float* __restrict__ wR, const float* __restrict__ bR) {
    int idx = blockIdx.x * blockDim.x + threadIdx.x;
    if (idx >= BT1 * NN) return;
    int n  = idx / BT1;
    int bt = idx - n * BT1;
    int b  = bt / T1;
    int t  = bt - b * T1;
    const float* xb = x + (size_t)(b * TT + t) * NN + n;
    float x0 = __ldg(xb);
    float x1 = __ldg(xb + NN);
    float x2 = __ldg(xb + 2 * NN);
    float4 o0, o1, o2, o3;

#define S1H(h, DST)                                                             \
    {                                                                           \
        float P = bP[h] + x0 * wP[h] + x1 * wP[16 + h] + x2 * wP[32 + h];       \
        float Q = bQ[h] + x0 * wQ[h] + x1 * wQ[16 + h] + x2 * wQ[32 + h];       \
        float R = bR[h] + x0 * wR[h] + x1 * wR[16 + h] + x2 * wR[32 + h];       \
        float s = 1.f / (1.f + __expf(-Q));                                     \
        DST = fmaxf(fmaf(P, s, R), 0.f);                                        \
    }
    S1H(0,  o0.x) S1H(1,  o0.y) S1H(2,  o0.z) S1H(3,  o0.w)
    S1H(4,  o1.x) S1H(5,  o1.y) S1H(6,  o1.z) S1H(7,  o1.w)
    S1H(8,  o2.x) S1H(9,  o2.y) S1H(10, o2.z) S1H(11, o2.w)
    S1H(12, o3.x) S1H(13, o3.y) S1H(14, o3.z) S1H(15, o3.w)
#undef S1H

    float4* out = (float4*)(g_h1 + (size_t)n * ROW + bt * HH);
    out[0] = o0; out[1] = o1; out[2] = o2; out[3] = o3;
}

// K5: edge aggregation. One thread per (edge, float4-chunk). 80 chunks/edge.
__global__ void k_agg() {
    int gid = blockIdx.x * blockDim.x + threadIdx.x;
    if (gid >= EE * 80) return;
    int e  = gid / 80;
    int it = gid - e * 80;
    int src = g_src[e];
    int dst = g_dst[e];
    float nrm = g_norm[e];
    float4 v = *((const float4*)(g_h1 + (size_t)src * ROW) + it);
    float4* d = (float4*)(g_agg + (size_t)dst * ROW) + it;
    asm volatile("red.global.add.v4.f32 [%0], {%1,%2,%3,%4};"
                 :: "l"(d), "f"(v.x * nrm), "f"(v.y * nrm), "f"(v.z * nrm), "f"(v.w * nrm)
                 : "memory");
}

// K6: cheb combine, IN PLACE into g_h1: h1 <- relu(h1 @ W0 + agg @ W1 + b)
// One thread per (n, bt). All-scalar (no local arrays).
__global__ void k_cheb(const float* __restrict__ cw, const float* __restrict__ cb) {
    __shared__ float sW0[256], sW1[256], sB[16];
    int tid = threadIdx.x;
    for (int i = tid; i < 256; i += blockDim.x) {
        sW0[i] = cw[i];
        sW1[i] = cw[256 + i];
    }
    if (tid < 16) sB[tid] = cb[tid];
    __syncthreads();
    int idx = blockIdx.x * blockDim.x + tid;
    if (idx >= BT1 * NN) return;
    int n  = idx / BT1;
    int bt = idx - n * BT1;
    size_t off = (size_t)n * ROW + bt * HH;
    float* r0 = g_h1 + off;          // read AND write (in place)
    const float* r1 = g_agg + off;

#define DECL_ACC(h) float acc##h = sB[h];
    RPT16A(DECL_ACC)
#undef DECL_ACC

#define ACC(h) acc##h = fmaf(av, w0[h], fmaf(gv, w1[h], acc##h));
#define STEP(c)                                                   \
    {                                                             \
        float av = r0[c], gv = r1[c];                             \
        const float* w0 = &sW0[(c) * 16];                         \
        const float* w1 = &sW1[(c) * 16];                         \
        RPT16B(ACC)                                               \
    }
    RPT16A(STEP)
#undef STEP
#undef ACC

#define WR(h) r0[h] = fmaxf(acc##h, 0.f);
    RPT16A(WR)
#undef WR
}

// K7: temporal conv 2 (GLU 16->16) + mean over t + linear, fused.
// 8 threads per (b, n); thread p owns output channels 2p, 2p+1.
// All-scalar; final linear reduced with shuffles across the 8-thread group.
__global__ __launch_bounds__(256) void k_stage4(
    const float* __restrict__ wP, const float* __restrict__ bP,
    const float* __restrict__ wQ, const float* __restrict__ bQ,
    const float* __restrict__ wR, const float* __restrict__ bR,
    const float* __restrict__ lw, const float* __restrict__ lb,
    float* __restrict__ out) {
    __shared__ float sWP[768], sWQ[768], sWR[768];  // [k][c][h]
    __shared__ float sBP[16], sBQ[16], sBR[16], sLW[32], sLB[2];
    int tid = threadIdx.x;
    for (int i = tid; i < 768; i += 256) {
        sWP[i] = wP[i];
        sWQ[i] = wQ[i];
        sWR[i] = wR[i];
    }
    if (tid < 16) { sBP[tid] = bP[tid]; sBQ[tid] = bQ[tid]; sBR[tid] = bR[tid]; }
    if (tid < 32) sLW[tid] = lw[tid];
    if (tid < 2)  sLB[tid] = lb[tid];
    __syncthreads();

    int gid = blockIdx.x * 256 + tid;        // exactly BB*NN*8 = 800000 threads
    int g = gid >> 3;                        // (b, n) group
    int p = gid & 7;                         // channel pair
    int b = g / NN;
    int n = g - b * NN;
    const float* row = g_h1 + (size_t)n * ROW + b * (T1 * HH);
    int h0 = 2 * p, h1 = 2 * p + 1;

    float bp0 = sBP[h0], bp1 = sBP[h1];
    float bq0 = sBQ[h0], bq1 = sBQ[h1];
    float br0 = sBR[h0], br1 = sBR[h1];
    float m0 = 0.f, m1 = 0.f;

#pragma unroll 1
    for (int t = 0; t < T2; t++) {
        float P0 = bp0, P1 = bp1, Q0 = bq0, Q1 = bq1, R0 = br0, R1 = br1;
        const float* xr = row + t * HH;
#pragma unroll
        for (int k = 0; k < 3; k++) {
#pragma unroll
            for (int c = 0; c < 16; c++) {
                float xv = xr[k * HH + c];
                int wi = k * 256 + c * 16;
                P0 = fmaf(xv, sWP[wi + h0], P0);
                P1 = fmaf(xv, sWP[wi + h1], P1);
                Q0 = fmaf(xv, sWQ[wi + h0], Q0);
                Q1 = fmaf(xv, sWQ[wi + h1], Q1);
                R0 = fmaf(xv, sWR[wi + h0], R0);
                R1 = fmaf(xv, sWR[wi + h1], R1);
            }
        }
        float s0 = 1.f / (1.f + __expf(-Q0));
        float s1 = 1.f / (1.f + __expf(-Q1));
        m0 += fmaxf(fmaf(P0, s0, R0), 0.f);
        m1 += fmaxf(fmaf(P1, s1, R1), 0.f);
    }

    m0 *= 0.125f;
    m1 *= 0.125f;
    float o0 = m0 * sLW[2 * h0]     + m1 * sLW[2 * h1];
    float o1 = m0 * sLW[2 * h0 + 1] + m1 * sLW[2 * h1 + 1];
#pragma unroll
    for (int s = 4; s > 0; s >>= 1) {
        o0 += __shfl_down_sync(0xFFFFFFFFu, o0, s, 8);
        o1 += __shfl_down_sync(0xFFFFFFFFu, o1, s, 8);
    }
    if (p == 0) ((float2*)out)[g] = make_float2(o0 + sLB[0], o1 + sLB[1]);
}

// ---------------------------------------------------------------------------
extern "C" void kernel_launch(void* const* d_in, const int* in_sizes, int n_in,
                              void* d_out, int out_size) {
    const float* x   = (const float*)d_in[0];
    const int*   eiw = (const int*)d_in[1];   // edge_index words (int32 or int64)
    const float* ew  = (const float*)d_in[2];
    const float* tc1Pw = (const float*)d_in[3];
    const float* tc1Pb = (const float*)d_in[4];
    const float* tc1Qw = (const float*)d_in[5];
    const float* tc1Qb = (const float*)d_in[6];
    const float* tc1Rw = (const float*)d_in[7];
    const float* tc1Rb = (const float*)d_in[8];
    const float* tc2Pw = (const float*)d_in[9];
    const float* tc2Pb = (const float*)d_in[10];
    const float* tc2Qw = (const float*)d_in[11];
    const float* tc2Qb = (const float*)d_in[12];
    const float* tc2Rw = (const float*)d_in[13];
    const float* tc2Rb = (const float*)d_in[14];
    const float* chebw = (const float*)d_in[15];
    const float* chebb = (const float*)d_in[16];
    const float* linw  = (const float*)d_in[17];
    const float* linb  = (const float*)d_in[18];
    float* out = (float*)d_out;

    const int zeroN = (NN * ROW) / 4;
    k_zero<<<(zeroN + 255) / 256, 256>>>();
    k_detect<<<16, 256>>>(eiw);
    k_convert<<<(EE + 255) / 256, 256>>>(eiw);
    k_deg<<<(EE + 255) / 256, 256>>>(ew);
    k_dis<<<(NN + 255) / 256, 256>>>();
    k_norm<<<(EE + 255) / 256, 256>>>(ew);
    k_stage1<<<(BT1 * NN + 255) / 256, 256>>>(x, tc1Pw, tc1Pb, tc1Qw, tc1Qb, tc1Rw, tc1Rb);
    k_agg<<<(EE * 80 + 255) / 256, 256>>>();
    k_cheb<<<(BT1 * NN + 255) / 256, 256>>>(chebw, chebb);
    k_stage4<<<(BB * NN * 8) / 256, 256>>>(tc2Pw, tc2Pb, tc2Qw, tc2Qb, tc2Rw, tc2Rb,
                                           linw, linb, out);
}

// round 6
// speedup vs baseline: 1.2638x; 1.2638x over previous
#include <cuda_runtime.h>
#include <cuda_bf16.h>

// Problem constants
#define NN 50000
#define EE 800000
#define BB 2
#define TT 12
#define HH 16
#define T1 10          // T-2
#define T2 8           // T-4
#define BT1 (BB*T1)    // 20
#define ROW (BT1*HH)   // 320 floats per node
#define NB  ((NN + 255) / 256)   // scan blocks = 196

// Scratch (node-major layout: [n][b][t][h]).  h2 overwrites g_h1 in place.
__device__ float g_h1[(size_t)NN * ROW];
__device__ float g_agg[(size_t)NN * ROW];
__device__ float g_deg[NN];
__device__ float g_dis[NN];
__device__ int   g_src[EE];
__device__ int   g_dst[EE];
__device__ int   g_cnt[NN];       // in-degree (by dst)
__device__ int   g_exc[NN];       // block-local exclusive scan
__device__ int   g_bsum[NB];      // per-block sums -> exclusive scanned
__device__ int   g_off[NN + 1];   // CSR row offsets (by dst)
__device__ int   g_fill[NN];      // bump cursors for scatter
__device__ int   g_esrc[EE];      // src sorted by dst
__device__ float g_enorm[EE];     // norm sorted by dst
__device__ int   g_oddnz;         // >0 => edge_index is int32; ==0 => int64

// Two identical repeat macros so they can nest.
#define RPT16A(M) M(0) M(1) M(2) M(3) M(4) M(5) M(6) M(7) \
                  M(8) M(9) M(10) M(11) M(12) M(13) M(14) M(15)
#define RPT16B(M) M(0) M(1) M(2) M(3) M(4) M(5) M(6) M(7) \
                  M(8) M(9) M(10) M(11) M(12) M(13) M(14) M(15)

// ---------------------------------------------------------------------------
// K0: zero deg + cnt + detector
__global__ void k_init() {
    int i = blockIdx.x * blockDim.x + threadIdx.x;
    if (i == 0) g_oddnz = 0;
    if (i < NN) { g_deg[i] = 0.f; g_cnt[i] = 0; }
}

// K0b: detect dtype of edge_index (odd int32 words all zero <=> int64).
__global__ void k_detect(const int* __restrict__ w) {
    int i = blockIdx.x * blockDim.x + threadIdx.x;   // 4096 threads
    int v = w[2 * i + 1];
    unsigned ballot = __ballot_sync(0xFFFFFFFFu, v != 0);
    if ((threadIdx.x & 31) == 0 && ballot) atomicAdd(&g_oddnz, __popc(ballot));
}

// K0c: unpack src/dst, accumulate weighted degree (by src) and in-count (by dst)
__global__ void k_convert(const int* __restrict__ w, const float* __restrict__ ew) {
    int e = blockIdx.x * blockDim.x + threadIdx.x;
    if (e >= EE) return;
    int src, dst;
    if (g_oddnz == 0) {  // int64
        src = w[2 * e];
        dst = w[2 * EE + 2 * e];
    } else {             // int32
        src = w[e];
        dst = w[EE + e];
    }
    g_src[e] = src;
    g_dst[e] = dst;
    atomicAdd(&g_deg[src], ew[e]);
    atomicAdd(&g_cnt[dst], 1);
}

// Scan pass 1: per-block exclusive scan of cnt, emit block sums
__global__ void k_scan_part() {
    __shared__ int s[256];
    int tid = threadIdx.x;
    int i = blockIdx.x * 256 + tid;
    int v = (i < NN) ? g_cnt[i] : 0;
    s[tid] = v;
    __syncthreads();
#pragma unroll
    for (int d = 1; d < 256; d <<= 1) {
        int t = (tid >= d) ? s[tid - d] : 0;
        __syncthreads();
        s[tid] += t;
        __syncthreads();
    }
    if (i < NN) g_exc[i] = s[tid] - v;
    if (tid == 255) g_bsum[blockIdx.x] = s[255];
}

// Scan pass 2: exclusive scan of block sums (single block)
__global__ void k_scan_top() {
    __shared__ int s[256];
    int tid = threadIdx.x;
    int v = (tid < NB) ? g_bsum[tid] : 0;
    s[tid] = v;
    __syncthreads();
#pragma unroll
    for (int d = 1; d < 256; d <<= 1) {
        int t = (tid >= d) ? s[tid - d] : 0;
        __syncthreads();
        s[tid] += t;
        __syncthreads();
    }
    if (tid < NB) g_bsum[tid] = s[tid] - v;
}

// Scan pass 3: final offsets + fill cursors
__global__ void k_scan_add() {
    int i = blockIdx.x * blockDim.x + threadIdx.x;
    if (i >= NN) return;
    int o = g_exc[i] + g_bsum[i >> 8];
    g_off[i] = o;
    g_fill[i] = o;
    if (i == 0) g_off[NN] = EE;
}

// dis = deg>0 ? rsqrt(max(deg,1e-12)) : 0
__global__ void k_dis() {
    int n = blockIdx.x * blockDim.x + threadIdx.x;
    if (n >= NN) return;
    float d = g_deg[n];
    g_dis[n] = (d > 0.f) ? rsqrtf(fmaxf(d, 1e-12f)) : 0.f;
}

// Scatter: CSR-sorted (src, norm) by dst
__global__ void k_scatter(const float* __restrict__ ew) {
    int e = blockIdx.x * blockDim.x + threadIdx.x;
    if (e >= EE) return;
    int src = g_src[e];
    int dst = g_dst[e];
    float nrm = -g_dis[src] * ew[e] * g_dis[dst];
    int pos = atomicAdd(&g_fill[dst], 1);
    g_esrc[pos] = src;
    g_enorm[pos] = nrm;
}

// K4: temporal conv 1 (GLU), C_IN=1 -> H=16.
__global__ void k_stage1(const float* __restrict__ x,
                         const float* __restrict__ wP, const float* __restrict__ bP,
                         const float* __restrict__ wQ, const float* __restrict__ bQ,
                         const float* __restrict__ wR, const float* __restrict__ bR) {
    int idx = blockIdx.x * blockDim.x + threadIdx.x;
    if (idx >= BT1 * NN) return;
    int n  = idx / BT1;
    int bt = idx - n * BT1;
    int b  = bt / T1;
    int t  = bt - b * T1;
    const float* xb = x + (size_t)(b * TT + t) * NN + n;
    float x0 = __ldg(xb);
    float x1 = __ldg(xb + NN);
    float x2 = __ldg(xb + 2 * NN);
    float4 o0, o1, o2, o3;

#define S1H(h, DST)                                                             \
    {                                                                           \
        float P = bP[h] + x0 * wP[h] + x1 * wP[16 + h] + x2 * wP[32 + h];       \
        float Q = bQ[h] + x0 * wQ[h] + x1 * wQ[16 + h] + x2 * wQ[32 + h];       \
        float R = bR[h] + x0 * wR[h] + x1 * wR[16 + h] + x2 * wR[32 + h];       \
        float s = 1.f / (1.f + __expf(-Q));                                     \
        DST = fmaxf(fmaf(P, s, R), 0.f);                                        \
    }
    S1H(0,  o0.x) S1H(1,  o0.y) S1H(2,  o0.z) S1H(3,  o0.w)
    S1H(4,  o1.x) S1H(5,  o1.y) S1H(6,  o1.z) S1H(7,  o1.w)
    S1H(8,  o2.x) S1H(9,  o2.y) S1H(10, o2.z) S1H(11, o2.w)
    S1H(12, o3.x) S1H(13, o3.y) S1H(14, o3.z) S1H(15, o3.w)
#undef S1H

    float4* out = (float4*)(g_h1 + (size_t)n * ROW + bt * HH);
    out[0] = o0; out[1] = o1; out[2] = o2; out[3] = o3;
}

// K5: CSR aggregation: agg[dst] = sum_{edges into dst} norm * h1[src].
// 80 threads per dst node (one float4 chunk each). Plain stores, no atomics.
__global__ void k_agg2() {
    int gid = blockIdx.x * blockDim.x + threadIdx.x;
    if (gid >= NN * 80) return;
    int n  = gid / 80;
    int it = gid - n * 80;
    int p   = g_off[n];
    int end = g_off[n + 1];
    float4 acc = make_float4(0.f, 0.f, 0.f, 0.f);
    for (; p < end; p++) {
        int   s = g_esrc[p];
        float w = g_enorm[p];
        float4 v = *((const float4*)(g_h1 + (size_t)s * ROW) + it);
        acc.x = fmaf(w, v.x, acc.x);
        acc.y = fmaf(w, v.y, acc.y);
        acc.z = fmaf(w, v.z, acc.z);
        acc.w = fmaf(w, v.w, acc.w);
    }
    ((float4*)(g_agg + (size_t)n * ROW))[it] = acc;
}

// K6: cheb combine, IN PLACE into g_h1: h1 <- relu(h1 @ W0 + agg @ W1 + b)
__global__ void k_cheb(const float* __restrict__ cw, const float* __restrict__ cb) {
    __shared__ float sW0[256], sW1[256], sB[16];
    int tid = threadIdx.x;
    for (int i = tid; i < 256; i += blockDim.x) {
        sW0[i] = cw[i];
        sW1[i] = cw[256 + i];
    }
    if (tid < 16) sB[tid] = cb[tid];
    __syncthreads();
    int idx = blockIdx.x * blockDim.x + tid;
    if (idx >= BT1 * NN) return;
    int n  = idx / BT1;
    int bt = idx - n * BT1;
    size_t off = (size_t)n * ROW + bt * HH;
    float* r0 = g_h1 + off;          // read AND write (in place)
    const float* r1 = g_agg + off;

#define DECL_ACC(h) float acc##h = sB[h];
    RPT16A(DECL_ACC)
#undef DECL_ACC

#define ACC(h) acc##h = fmaf(av, w0[h], fmaf(gv, w1[h], acc##h));
#define STEP(c)                                                   \
    {                                                             \
        float av = r0[c], gv = r1[c];                             \
        const float* w0 = &sW0[(c) * 16];                         \
        const float* w1 = &sW1[(c) * 16];                         \
        RPT16B(ACC)                                               \
    }
    RPT16A(STEP)
#undef STEP
#undef ACC

#define WR(h) r0[h] = fmaxf(acc##h, 0.f);
    RPT16A(WR)
#undef WR
}

// K7: temporal conv 2 (GLU 16->16) + mean over t + linear, fused.
// 8 threads per (b, n); thread p owns output channels 2p, 2p+1.
__global__ __launch_bounds__(256) void k_stage4(
    const float* __restrict__ wP, const float* __restrict__ bP,
    const float* __restrict__ wQ, const float* __restrict__ bQ,
    const float* __restrict__ wR, const float* __restrict__ bR,
    const float* __restrict__ lw, const float* __restrict__ lb,
    float* __restrict__ out) {
    __shared__ float sWP[768], sWQ[768], sWR[768];  // [k][c][h]
    __shared__ float sBP[16], sBQ[16], sBR[16], sLW[32], sLB[2];
    int tid = threadIdx.x;
    for (int i = tid; i < 768; i += 256) {
        sWP[i] = wP[i];
        sWQ[i] = wQ[i];
        sWR[i] = wR[i];
    }
    if (tid < 16) { sBP[tid] = bP[tid]; sBQ[tid] = bQ[tid]; sBR[tid] = bR[tid]; }
    if (tid < 32) sLW[tid] = lw[tid];
    if (tid < 2)  sLB[tid] = lb[tid];
    __syncthreads();

    int gid = blockIdx.x * 256 + tid;        // exactly BB*NN*8 = 800000 threads
    int g = gid >> 3;                        // (b, n) group
    int p = gid & 7;                         // channel pair
    int b = g / NN;
    int n = g - b * NN;
    const float* row = g_h1 + (size_t)n * ROW + b * (T1 * HH);
    int h0 = 2 * p, h1 = 2 * p + 1;

    float bp0 = sBP[h0], bp1 = sBP[h1];
    float bq0 = sBQ[h0], bq1 = sBQ[h1];
    float br0 = sBR[h0], br1 = sBR[h1];
    float m0 = 0.f, m1 = 0.f;

#pragma unroll 1
    for (int t = 0; t < T2; t++) {
        float P0 = bp0, P1 = bp1, Q0 = bq0, Q1 = bq1, R0 = br0, R1 = br1;
        const float* xr = row + t * HH;
#pragma unroll
        for (int k = 0; k < 3; k++) {
#pragma unroll
            for (int c = 0; c < 16; c++) {
                float xv = xr[k * HH + c];
                int wi = k * 256 + c * 16;
                P0 = fmaf(xv, sWP[wi + h0], P0);
                P1 = fmaf(xv, sWP[wi + h1], P1);
                Q0 = fmaf(xv, sWQ[wi + h0], Q0);
                Q1 = fmaf(xv, sWQ[wi + h1], Q1);
                R0 = fmaf(xv, sWR[wi + h0], R0);
                R1 = fmaf(xv, sWR[wi + h1], R1);
            }
        }
        float s0 = 1.f / (1.f + __expf(-Q0));
        float s1 = 1.f / (1.f + __expf(-Q1));
        m0 += fmaxf(fmaf(P0, s0, R0), 0.f);
        m1 += fmaxf(fmaf(P1, s1, R1), 0.f);
    }

    m0 *= 0.125f;
    m1 *= 0.125f;
    float o0 = m0 * sLW[2 * h0]     + m1 * sLW[2 * h1];
    float o1 = m0 * sLW[2 * h0 + 1] + m1 * sLW[2 * h1 + 1];
#pragma unroll
    for (int s = 4; s > 0; s >>= 1) {
        o0 += __shfl_down_sync(0xFFFFFFFFu, o0, s, 8);
        o1 += __shfl_down_sync(0xFFFFFFFFu, o1, s, 8);
    }
    if (p == 0) ((float2*)out)[g] = make_float2(o0 + sLB[0], o1 + sLB[1]);
}

// ---------------------------------------------------------------------------
extern "C" void kernel_launch(void* const* d_in, const int* in_sizes, int n_in,
                              void* d_out, int out_size) {
    const float* x   = (const float*)d_in[0];
    const int*   eiw = (const int*)d_in[1];   // edge_index words (int32 or int64)
    const float* ew  = (const float*)d_in[2];
    const float* tc1Pw = (const float*)d_in[3];
    const float* tc1Pb = (const float*)d_in[4];
    const float* tc1Qw = (const float*)d_in[5];
    const float* tc1Qb = (const float*)d_in[6];
    const float* tc1Rw = (const float*)d_in[7];
    const float* tc1Rb = (const float*)d_in[8];
    const float* tc2Pw = (const float*)d_in[9];
    const float* tc2Pb = (const float*)d_in[10];
    const float* tc2Qw = (const float*)d_in[11];
    const float* tc2Qb = (const float*)d_in[12];
    const float* tc2Rw = (const float*)d_in[13];
    const float* tc2Rb = (const float*)d_in[14];
    const float* chebw = (const float*)d_in[15];
    const float* chebb = (const float*)d_in[16];
    const float* linw  = (const float*)d_in[17];
    const float* linb  = (const float*)d_in[18];
    float* out = (float*)d_out;

    k_init<<<(NN + 255) / 256, 256>>>();
    k_detect<<<16, 256>>>(eiw);
    k_convert<<<(EE + 255) / 256, 256>>>(eiw, ew);
    k_scan_part<<<NB, 256>>>();
    k_scan_top<<<1, 256>>>();
    k_scan_add<<<(NN + 255) / 256, 256>>>();
    k_dis<<<(NN + 255) / 256, 256>>>();
    k_scatter<<<(EE + 255) / 256, 256>>>(ew);
    k_stage1<<<(BT1 * NN + 255) / 256, 256>>>(x, tc1Pw, tc1Pb, tc1Qw, tc1Qb, tc1Rw, tc1Rb);
    k_agg2<<<(NN * 80 + 255) / 256, 256>>>();
    k_cheb<<<(BT1 * NN + 255) / 256, 256>>>(chebw, chebb);
    k_stage4<<<(BB * NN * 8) / 256, 256>>>(tc2Pw, tc2Pb, tc2Qw, tc2Qb, tc2Rw, tc2Rb,
                                           linw, linb, out);
}

// round 8
// speedup vs baseline: 1.3474x; 1.0661x over previous
#include <cuda_runtime.h>
#include <cuda_bf16.h>

// Problem constants
#define NN 50000
#define EE 800000
#define BB 2
#define TT 12
#define HH 16
#define T1 10          // T-2
#define T2 8           // T-4
#define BT1 (BB*T1)    // 20
#define ROW (BT1*HH)   // 320 floats per node
#define NB  ((NN + 255) / 256)   // scan blocks = 196

// Scratch (node-major layout: [n][b][t][h]).
// g_h1: holds A = h1@W0 + b after stage1, then h2 (in place) after agg.
// g_agg: holds Bw = h1@W1 after stage1 (gather source).
__device__ float g_h1[(size_t)NN * ROW];
__device__ float g_agg[(size_t)NN * ROW];
__device__ float g_deg[NN];
__device__ float g_dis[NN];
__device__ int   g_src[EE];
__device__ int   g_dst[EE];
__device__ int   g_cnt[NN];       // in-degree (by dst)
__device__ int   g_exc[NN];       // block-local exclusive scan
__device__ int   g_bsum[NB];      // per-block sums -> exclusive scanned
__device__ int   g_off[NN + 1];   // CSR row offsets (by dst)
__device__ int   g_fill[NN];      // bump cursors for scatter
__device__ int   g_esrc[EE];      // src sorted by dst
__device__ float g_enorm[EE];     // norm sorted by dst
__device__ int   g_oddnz;         // >0 => edge_index is int32; ==0 => int64

// Two identical repeat macros so they can nest.
#define RPT16A(M) M(0) M(1) M(2) M(3) M(4) M(5) M(6) M(7) \
                  M(8) M(9) M(10) M(11) M(12) M(13) M(14) M(15)
#define RPT16B(M) M(0) M(1) M(2) M(3) M(4) M(5) M(6) M(7) \
                  M(8) M(9) M(10) M(11) M(12) M(13) M(14) M(15)

// ---------------------------------------------------------------------------
__global__ void k_init() {
    int i = blockIdx.x * blockDim.x + threadIdx.x;
    if (i == 0) g_oddnz = 0;
    if (i < NN) { g_deg[i] = 0.f; g_cnt[i] = 0; }
}

// Detect dtype of edge_index (odd int32 words all zero <=> int64).
__global__ void k_detect(const int* __restrict__ w) {
    int i = blockIdx.x * blockDim.x + threadIdx.x;   // 4096 threads
    int v = w[2 * i + 1];
    unsigned ballot = __ballot_sync(0xFFFFFFFFu, v != 0);
    if ((threadIdx.x & 31) == 0 && ballot) atomicAdd(&g_oddnz, __popc(ballot));
}

// Unpack src/dst, accumulate weighted degree (by src) and in-count (by dst)
__global__ void k_convert(const int* __restrict__ w, const float* __restrict__ ew) {
    int e = blockIdx.x * blockDim.x + threadIdx.x;
    if (e >= EE) return;
    int src, dst;
    if (g_oddnz == 0) {  // int64
        src = w[2 * e];
        dst = w[2 * EE + 2 * e];
    } else {             // int32
        src = w[e];
        dst = w[EE + e];
    }
    g_src[e] = src;
    g_dst[e] = dst;
    atomicAdd(&g_deg[src], ew[e]);
    atomicAdd(&g_cnt[dst], 1);
}

// Scan pass 1: per-block exclusive scan of cnt, emit block sums
__global__ void k_scan_part() {
    __shared__ int s[256];
    int tid = threadIdx.x;
    int i = blockIdx.x * 256 + tid;
    int v = (i < NN) ? g_cnt[i] : 0;
    s[tid] = v;
    __syncthreads();
#pragma unroll
    for (int d = 1; d < 256; d <<= 1) {
        int t = (tid >= d) ? s[tid - d] : 0;
        __syncthreads();
        s[tid] += t;
        __syncthreads();
    }
    if (i < NN) g_exc[i] = s[tid] - v;
    if (tid == 255) g_bsum[blockIdx.x] = s[255];
}

// Scan pass 2: exclusive scan of block sums (single block)
__global__ void k_scan_top() {
    __shared__ int s[256];
    int tid = threadIdx.x;
    int v = (tid < NB) ? g_bsum[tid] : 0;
    s[tid] = v;
    __syncthreads();
#pragma unroll
    for (int d = 1; d < 256; d <<= 1) {
        int t = (tid >= d) ? s[tid - d] : 0;
        __syncthreads();
        s[tid] += t;
        __syncthreads();
    }
    if (tid < NB) g_bsum[tid] = s[tid] - v;
}

// Scan pass 3: final offsets + fill cursors
__global__ void k_scan_add() {
    int i = blockIdx.x * blockDim.x + threadIdx.x;
    if (i >= NN) return;
    int o = g_exc[i] + g_bsum[i >> 8];
    g_off[i] = o;
    g_fill[i] = o;
    if (i == 0) g_off[NN] = EE;
}

// dis = deg>0 ? rsqrt(max(deg,1e-12)) : 0
__global__ void k_dis() {
    int n = blockIdx.x * blockDim.x + threadIdx.x;
    if (n >= NN) return;
    float d = g_deg[n];
    g_dis[n] = (d > 0.f) ? rsqrtf(fmaxf(d, 1e-12f)) : 0.f;
}

// Scatter: CSR-sorted (src, norm) by dst
__global__ void k_scatter(const float* __restrict__ ew) {
    int e = blockIdx.x * blockDim.x + threadIdx.x;
    if (e >= EE) return;
    int src = g_src[e];
    int dst = g_dst[e];
    float nrm = -g_dis[src] * ew[e] * g_dis[dst];
    int pos = atomicAdd(&g_fill[dst], 1);
    g_esrc[pos] = src;
    g_enorm[pos] = nrm;
}

// Stage 1: temporal conv (GLU, 1->16) fused with the Cheb weight transforms.
// Writes A = h1@W0 + cb  -> g_h1   (to be combined in place by k_agg3)
//        Bw = h1@W1      -> g_agg  (gather source)
__global__ void k_stage1(const float* __restrict__ x,
                         const float* __restrict__ wP, const float* __restrict__ bP,
                         const float* __restrict__ wQ, const float* __restrict__ bQ,
                         const float* __restrict__ wR, const float* __restrict__ bR,
                         const float* __restrict__ cw, const float* __restrict__ cb) {
    __shared__ float sW0[256], sW1[256], sCB[16];
    {
        int tid = threadIdx.x;
        for (int i = tid; i < 256; i += blockDim.x) {
            sW0[i] = cw[i];
            sW1[i] = cw[256 + i];
        }
        if (tid < 16) sCB[tid] = cb[tid];
        __syncthreads();
    }
    int idx = blockIdx.x * blockDim.x + threadIdx.x;
    if (idx >= BT1 * NN) return;
    int n  = idx / BT1;
    int bt = idx - n * BT1;
    int b  = bt / T1;
    int t  = bt - b * T1;
    const float* xb = x + (size_t)(b * TT + t) * NN + n;
    float x0 = __ldg(xb);
    float x1 = __ldg(xb + NN);
    float x2 = __ldg(xb + 2 * NN);

#define S1H(h)                                                                  \
    float v##h;                                                                 \
    {                                                                           \
        float P = bP[h] + x0 * wP[h] + x1 * wP[16 + h] + x2 * wP[32 + h];       \
        float Q = bQ[h] + x0 * wQ[h] + x1 * wQ[16 + h] + x2 * wQ[32 + h];       \
        float R = bR[h] + x0 * wR[h] + x1 * wR[16 + h] + x2 * wR[32 + h];       \
        float s = 1.f / (1.f + __expf(-Q));                                     \
        v##h = fmaxf(fmaf(P, s, R), 0.f);                                       \
    }
    RPT16A(S1H)
#undef S1H

#define DECL(h) float a##h = sCB[h]; float g##h = 0.f;
    RPT16A(DECL)
#undef DECL

#define ACC(h) a##h = fmaf(vc, w0[h], a##h); g##h = fmaf(vc, w1[h], g##h);
#define STEP(c)                                                   \
    {                                                             \
        float vc = v##c;                                          \
        const float* w0 = &sW0[(c) * 16];                         \
        const float* w1 = &sW1[(c) * 16];                         \
        RPT16B(ACC)                                               \
    }
    RPT16A(STEP)
#undef STEP
#undef ACC

    float4* oa = (float4*)(g_h1 + (size_t)n * ROW + bt * HH);
    oa[0] = make_float4(a0, a1, a2, a3);
    oa[1] = make_float4(a4, a5, a6, a7);
    oa[2] = make_float4(a8, a9, a10, a11);
    oa[3] = make_float4(a12, a13, a14, a15);
    float4* og = (float4*)(g_agg + (size_t)n * ROW + bt * HH);
    og[0] = make_float4(g0, g1, g2, g3);
    og[1] = make_float4(g4, g5, g6, g7);
    og[2] = make_float4(g8, g9, g10, g11);
    og[3] = make_float4(g12, g13, g14, g15);
}

// CSR aggregation + Cheb combine epilogue.
// 8 threads per dst node; thread j owns float4 chunks {j, j+8, ..., j+72}.
// h2[n] = relu(A[n] + sum_{edges into n} norm * Bw[src]), written in place to g_h1.
__global__ __launch_bounds__(256) void k_agg3() {
    int gid = blockIdx.x * 256 + threadIdx.x;
    if (gid >= NN * 8) return;
    int n = gid >> 3;
    int j = gid & 7;
    int p   = g_off[n];
    int end = g_off[n + 1];
    float4 acc[10];
#pragma unroll
    for (int i = 0; i < 10; i++) acc[i] = make_float4(0.f, 0.f, 0.f, 0.f);
    for (; p < end; p++) {
        int   s = g_esrc[p];
        float w = g_enorm[p];
        const float4* src = (const float4*)(g_agg + (size_t)s * ROW) + j;
#pragma unroll
        for (int i = 0; i < 10; i++) {
            float4 v = src[8 * i];
            acc[i].x = fmaf(w, v.x, acc[i].x);
            acc[i].y = fmaf(w, v.y, acc[i].y);
            acc[i].z = fmaf(w, v.z, acc[i].z);
            acc[i].w = fmaf(w, v.w, acc[i].w);
        }
    }
    float4* an = (float4*)(g_h1 + (size_t)n * ROW) + j;
#pragma unroll
    for (int i = 0; i < 10; i++) {
        float4 a = an[8 * i];
        a.x = fmaxf(a.x + acc[i].x, 0.f);
        a.y = fmaxf(a.y + acc[i].y, 0.f);
        a.z = fmaxf(a.z + acc[i].z, 0.f);
        a.w = fmaxf(a.w + acc[i].w, 0.f);
        an[8 * i] = a;
    }
}

// Stage 4: temporal conv 2 (GLU 16->16) + mean over t + linear, fused.
// 8 threads per (b, n); thread p owns output channels 2p, 2p+1.
__global__ __launch_bounds__(256) void k_stage4(
    const float* __restrict__ wP, const float* __restrict__ bP,
    const float* __restrict__ wQ, const float* __restrict__ bQ,
    const float* __restrict__ wR, const float* __restrict__ bR,
    const float* __restrict__ lw, const float* __restrict__ lb,
    float* __restrict__ out) {
    __shared__ float sWP[768], sWQ[768], sWR[768];  // [k][c][h]
    __shared__ float sBP[16], sBQ[16], sBR[16], sLW[32], sLB[2];
    int tid = threadIdx.x;
    for (int i = tid; i < 768; i += 256) {
        sWP[i] = wP[i];
        sWQ[i] = wQ[i];
        sWR[i] = wR[i];
    }
    if (tid < 16) { sBP[tid] = bP[tid]; sBQ[tid] = bQ[tid]; sBR[tid] = bR[tid]; }
    if (tid < 32) sLW[tid] = lw[tid];
    if (tid < 2)  sLB[tid] = lb[tid];
    __syncthreads();

    int gid = blockIdx.x * 256 + tid;        // exactly BB*NN*8 = 800000 threads
    int g = gid >> 3;                        // (b, n) group
    int p = gid & 7;                         // channel pair
    int b = g / NN;
    int n = g - b * NN;
    const float* row = g_h1 + (size_t)n * ROW + b * (T1 * HH);
    int h0 = 2 * p, h1 = 2 * p + 1;

    float bp0 = sBP[h0], bp1 = sBP[h1];
    float bq0 = sBQ[h0], bq1 = sBQ[h1];
    float br0 = sBR[h0], br1 = sBR[h1];
    float m0 = 0.f, m1 = 0.f;

#pragma unroll 1
    for (int t = 0; t < T2; t++) {
        float P0 = bp0, P1 = bp1, Q0 = bq0, Q1 = bq1, R0 = br0, R1 = br1;
        const float* xr = row + t * HH;
#pragma unroll
        for (int k = 0; k < 3; k++) {
#pragma unroll
            for (int c = 0; c < 16; c++) {
                float xv = xr[k * HH + c];
                int wi = k * 256 + c * 16;
                P0 = fmaf(xv, sWP[wi + h0], P0);
                P1 = fmaf(xv, sWP[wi + h1], P1);
                Q0 = fmaf(xv, sWQ[wi + h0], Q0);
                Q1 = fmaf(xv, sWQ[wi + h1], Q1);
                R0 = fmaf(xv, sWR[wi + h0], R0);
                R1 = fmaf(xv, sWR[wi + h1], R1);
            }
        }
        float s0 = 1.f / (1.f + __expf(-Q0));
        float s1 = 1.f / (1.f + __expf(-Q1));
        m0 += fmaxf(fmaf(P0, s0, R0), 0.f);
        m1 += fmaxf(fmaf(P1, s1, R1), 0.f);
    }

    m0 *= 0.125f;
    m1 *= 0.125f;
    float o0 = m0 * sLW[2 * h0]     + m1 * sLW[2 * h1];
    float o1 = m0 * sLW[2 * h0 + 1] + m1 * sLW[2 * h1 + 1];
#pragma unroll
    for (int s = 4; s > 0; s >>= 1) {
        o0 += __shfl_down_sync(0xFFFFFFFFu, o0, s, 8);
        o1 += __shfl_down_sync(0xFFFFFFFFu, o1, s, 8);
    }
    if (p == 0) ((float2*)out)[g] = make_float2(o0 + sLB[0], o1 + sLB[1]);
}

// ---------------------------------------------------------------------------
extern "C" void kernel_launch(void* const* d_in, const int* in_sizes, int n_in,
                              void* d_out, int out_size) {
    const float* x   = (const float*)d_in[0];
    const int*   eiw = (const int*)d_in[1];   // edge_index words (int32 or int64)
    const float* ew  = (const float*)d_in[2];
    const float* tc1Pw = (const float*)d_in[3];
    const float* tc1Pb = (const float*)d_in[4];
    const float* tc1Qw = (const float*)d_in[5];
    const float* tc1Qb = (const float*)d_in[6];
    const float* tc1Rw = (const float*)d_in[7];
    const float* tc1Rb = (const float*)d_in[8];
    const float* tc2Pw = (const float*)d_in[9];
    const float* tc2Pb = (const float*)d_in[10];
    const float* tc2Qw = (const float*)d_in[11];
    const float* tc2Qb = (const float*)d_in[12];
    const float* tc2Rw = (const float*)d_in[13];
    const float* tc2Rb = (const float*)d_in[14];
    const float* chebw = (const float*)d_in[15];
    const float* chebb = (const float*)d_in[16];
    const float* linw  = (const float*)d_in[17];
    const float* linb  = (const float*)d_in[18];
    float* out = (float*)d_out;

    k_init<<<(NN + 255) / 256, 256>>>();
    k_detect<<<16, 256>>>(eiw);
    k_convert<<<(EE + 255) / 256, 256>>>(eiw, ew);
    k_scan_part<<<NB, 256>>>();
    k_scan_top<<<1, 256>>>();
    k_scan_add<<<(NN + 255) / 256, 256>>>();
    k_dis<<<(NN + 255) / 256, 256>>>();
    k_scatter<<<(EE + 255) / 256, 256>>>(ew);
    k_stage1<<<(BT1 * NN + 255) / 256, 256>>>(x, tc1Pw, tc1Pb, tc1Qw, tc1Qb, tc1Rw, tc1Rb,
                                              chebw, chebb);
    k_agg3<<<(NN * 8 + 255) / 256, 256>>>();
    k_stage4<<<(BB * NN * 8) / 256, 256>>>(tc2Pw, tc2Pb, tc2Qw, tc2Qb, tc2Rw, tc2Rb,
                                           linw, linb, out);
}